// round 16
// baseline (speedup 1.0000x reference)
#include <cuda_runtime.h>
#include <cuda_bf16.h>
#include <math.h>
#include <stdint.h>

#define B_    8
#define L_    2048
#define D_    256
#define N_    16
#define R_    16
#define CL    32          // scan chunk length
#define NC    (L_/CL)     // 64 chunks
#define NSEG  8           // combine segments
#define SEGC  (NC/NSEG)   // 8 chunks per combine segment
#define NP    80          // projection outputs per row

typedef unsigned long long ull;

// ---------------- scratch (device globals) ----------------
__device__ float    g_P80    [B_*L_*NP];
__device__ float    g_P      [B_*NC*N_*D_];
__device__ float    g_H      [B_*NC*N_*D_];
__device__ float    g_hs     [B_*NC*N_*D_];
__device__ uint32_t g_y16    [B_*L_*D_];
__device__ uint32_t g_W16    [D_*D_];

// FAST softplus (MUFU EX2/LG2 — library log1pf cost ~70 µs, R13->R14)
__device__ __forceinline__ float softplusf(float v) {
    return v > 20.0f ? v : __logf(1.0f + __expf(v));
}

__device__ __forceinline__ uint32_t pack_hilo(float v) {
    __nv_bfloat16 h = __float2bfloat16(v);
    __nv_bfloat16 l = __float2bfloat16(v - __bfloat162float(h));
    return (uint32_t)__bfloat16_as_ushort(h) |
           ((uint32_t)__bfloat16_as_ushort(l) << 16);
}

// ---------------- packed f32x2 helpers ----------------
__device__ __forceinline__ ull pack2(float lo, float hi) {
    ull r;
    asm("mov.b64 %0, {%1, %2};" : "=l"(r) : "f"(lo), "f"(hi));
    return r;
}
__device__ __forceinline__ void unpack2(ull v, float& lo, float& hi) {
    asm("mov.b64 {%0, %1}, %2;" : "=f"(lo), "=f"(hi) : "l"(v));
}
__device__ __forceinline__ ull mul2(ull a, ull b) {
    ull d;
    asm("mul.rn.f32x2 %0, %1, %2;" : "=l"(d) : "l"(a), "l"(b));
    return d;
}
__device__ __forceinline__ ull fma2(ull a, ull b, ull c) {
    ull d;
    asm("fma.rn.f32x2 %0, %1, %2, %3;" : "=l"(d) : "l"(a), "l"(b), "l"(c));
    return d;
}
__device__ __forceinline__ void powers16_p2(float p1, ull e2[8]) {
    const float p1sq = p1 * p1;
    e2[0] = pack2(p1, p1sq);
    const ull pstep = pack2(p1sq, p1sq);
    #pragma unroll
    for (int k = 1; k < 8; ++k) e2[k] = mul2(e2[k-1], pstep);
}

__device__ __forceinline__ float check_A(const float* __restrict__ A_log,
                                         int d, bool& fast) {
    float a0 = -__expf(__ldg(A_log + d*N_));
    fast = true;
    #pragma unroll
    for (int n = 1; n < N_; ++n) {
        float an = -__expf(__ldg(A_log + d*N_ + n));
        fast = fast && (fabsf(an - a0*(float)(n+1)) <= 1e-4f*(float)(n+1));
    }
    return a0;
}

// ---------------------------------------------------------------------------
// Kernel 1: projgemm — P80 = x @ [Wxp;Wxb;0]^T via mma.sync bf16 split.
// Also packs W_out into g_W16 (2 elements/thread across the 128 blocks).
// W rows converted inline from fp32 (no prepacked Wall).
// ---------------------------------------------------------------------------
#define GP 72   // smem pitch in bf16 elements

__device__ __forceinline__ void mma_bf16(float dd[4],
                                         const uint32_t a[4],
                                         const uint32_t b[2]) {
    asm volatile(
        "mma.sync.aligned.m16n8k16.row.col.f32.bf16.bf16.f32 "
        "{%0,%1,%2,%3}, {%4,%5,%6,%7}, {%8,%9}, {%0,%1,%2,%3};"
        : "+f"(dd[0]), "+f"(dd[1]), "+f"(dd[2]), "+f"(dd[3])
        : "r"(a[0]), "r"(a[1]), "r"(a[2]), "r"(a[3]), "r"(b[0]), "r"(b[1]));
}

__device__ __forceinline__ float2 wall_row(const float* __restrict__ Wxp,
                                           const float* __restrict__ Wxb,
                                           int row, int off) {
    if (row < 64)  return *reinterpret_cast<const float2*>(Wxp + row*D_ + off);
    if (row < 80)  return *reinterpret_cast<const float2*>(Wxb + (row-64)*D_ + off);
    return make_float2(0.f, 0.f);
}

__global__ __launch_bounds__(256) void projgemm_kernel(
    const float* __restrict__ x,   const float* __restrict__ Wxp,
    const float* __restrict__ Wxb, const float* __restrict__ Wout)
{
    extern __shared__ __nv_bfloat16 sm[];
    __nv_bfloat16* sA_hi = sm;
    __nv_bfloat16* sA_lo = sm + 128*GP;
    __nv_bfloat16* sB_hi = sm + 2*128*GP;
    __nv_bfloat16* sB_lo = sm + 3*128*GP;

    const int tid  = threadIdx.x;
    const int wid  = tid >> 5;
    const int lane = tid & 31;
    const int gid  = lane >> 2;
    const int t4   = lane & 3;

    // side job: pack W_out for the final GEMM (done long before gemm launches)
    {
        const int gidx = blockIdx.y*256 + tid;          // 0..32767
        g_W16[gidx]         = pack_hilo(Wout[gidx]);
        g_W16[gidx + 32768] = pack_hilo(Wout[gidx + 32768]);
    }

    const int m0 = blockIdx.y * 128;
    const int wm = (wid >> 2) * 64;
    const int wn = (wid & 3) * 32;

    float acc[4][4][4];
    #pragma unroll
    for (int i = 0; i < 4; ++i)
        #pragma unroll
        for (int j = 0; j < 4; ++j)
            #pragma unroll
            for (int q = 0; q < 4; ++q) acc[i][j][q] = 0.f;

    const int lrow = tid >> 5;
    const int lpc  = tid & 31;

    float2 pa[16], pb[16];
    #pragma unroll
    for (int rr = 0; rr < 16; ++rr) {
        const int row = lrow + rr*8;
        pa[rr] = *reinterpret_cast<const float2*>(x + (size_t)(m0 + row)*D_ + lpc*2);
        pb[rr] = wall_row(Wxp, Wxb, row, lpc*2);
    }

    for (int kc = 0; kc < 256; kc += 64) {
        #pragma unroll
        for (int rr = 0; rr < 16; ++rr) {
            const int row = lrow + rr*8;
            const int soff = row*GP + lpc*2;
            __nv_bfloat16 ahx = __float2bfloat16(pa[rr].x);
            __nv_bfloat16 ahy = __float2bfloat16(pa[rr].y);
            __nv_bfloat16 alx = __float2bfloat16(pa[rr].x - __bfloat162float(ahx));
            __nv_bfloat16 aly = __float2bfloat16(pa[rr].y - __bfloat162float(ahy));
            *reinterpret_cast<__nv_bfloat162*>(sA_hi + soff) = __nv_bfloat162(ahx, ahy);
            *reinterpret_cast<__nv_bfloat162*>(sA_lo + soff) = __nv_bfloat162(alx, aly);
            __nv_bfloat16 bhx = __float2bfloat16(pb[rr].x);
            __nv_bfloat16 bhy = __float2bfloat16(pb[rr].y);
            __nv_bfloat16 blx = __float2bfloat16(pb[rr].x - __bfloat162float(bhx));
            __nv_bfloat16 bly = __float2bfloat16(pb[rr].y - __bfloat162float(bhy));
            *reinterpret_cast<__nv_bfloat162*>(sB_hi + soff) = __nv_bfloat162(bhx, bhy);
            *reinterpret_cast<__nv_bfloat162*>(sB_lo + soff) = __nv_bfloat162(blx, bly);
        }
        __syncthreads();

        if (kc < 192) {
            #pragma unroll
            for (int rr = 0; rr < 16; ++rr) {
                const int row = lrow + rr*8;
                pa[rr] = *reinterpret_cast<const float2*>(
                    x + (size_t)(m0 + row)*D_ + kc + 64 + lpc*2);
                pb[rr] = wall_row(Wxp, Wxb, row, kc + 64 + lpc*2);
            }
        }

        #pragma unroll
        for (int ks = 0; ks < 4; ++ks) {
            const int k0 = ks*16;
            uint32_t a_hi[4][4], a_lo[4][4], b_hi[4][2], b_lo[4][2];
            #pragma unroll
            for (int mf = 0; mf < 4; ++mf) {
                const int r0 = wm + mf*16 + gid;
                const int c0 = k0 + t4*2;
                a_hi[mf][0] = *reinterpret_cast<const uint32_t*>(sA_hi + (r0    )*GP + c0    );
                a_hi[mf][1] = *reinterpret_cast<const uint32_t*>(sA_hi + (r0 + 8)*GP + c0    );
                a_hi[mf][2] = *reinterpret_cast<const uint32_t*>(sA_hi + (r0    )*GP + c0 + 8);
                a_hi[mf][3] = *reinterpret_cast<const uint32_t*>(sA_hi + (r0 + 8)*GP + c0 + 8);
                a_lo[mf][0] = *reinterpret_cast<const uint32_t*>(sA_lo + (r0    )*GP + c0    );
                a_lo[mf][1] = *reinterpret_cast<const uint32_t*>(sA_lo + (r0 + 8)*GP + c0    );
                a_lo[mf][2] = *reinterpret_cast<const uint32_t*>(sA_lo + (r0    )*GP + c0 + 8);
                a_lo[mf][3] = *reinterpret_cast<const uint32_t*>(sA_lo + (r0 + 8)*GP + c0 + 8);
            }
            #pragma unroll
            for (int nf = 0; nf < 4; ++nf) {
                const int nr = wn + nf*8 + gid;
                const int c0 = k0 + t4*2;
                b_hi[nf][0] = *reinterpret_cast<const uint32_t*>(sB_hi + nr*GP + c0    );
                b_hi[nf][1] = *reinterpret_cast<const uint32_t*>(sB_hi + nr*GP + c0 + 8);
                b_lo[nf][0] = *reinterpret_cast<const uint32_t*>(sB_lo + nr*GP + c0    );
                b_lo[nf][1] = *reinterpret_cast<const uint32_t*>(sB_lo + nr*GP + c0 + 8);
            }
            #pragma unroll
            for (int mf = 0; mf < 4; ++mf)
                #pragma unroll
                for (int nf = 0; nf < 4; ++nf) {
                    mma_bf16(acc[mf][nf], a_hi[mf], b_hi[nf]);
                    mma_bf16(acc[mf][nf], a_hi[mf], b_lo[nf]);
                    mma_bf16(acc[mf][nf], a_lo[mf], b_hi[nf]);
                }
        }
        __syncthreads();
    }

    #pragma unroll
    for (int mf = 0; mf < 4; ++mf) {
        const int mrow = m0 + wm + mf*16 + gid;
        #pragma unroll
        for (int nf = 0; nf < 4; ++nf) {
            const int ncol = wn + nf*8 + t4*2;
            if (ncol < NP) {
                *reinterpret_cast<float2*>(g_P80 + (size_t)mrow*NP + ncol) =
                    make_float2(acc[mf][nf][0], acc[mf][nf][1]);
                *reinterpret_cast<float2*>(g_P80 + (size_t)(mrow + 8)*NP + ncol) =
                    make_float2(acc[mf][nf][2], acc[mf][nf][3]);
            }
        }
    }
}

// ---------------------------------------------------------------------------
// Kernel 2: scan1 — local recurrence from h=0; emits ONLY P and H.
// ---------------------------------------------------------------------------
__global__ __launch_bounds__(256) void scan1_kernel(
    const float* __restrict__ x, const float* __restrict__ Wdt,
    const float* __restrict__ bdt, const float* __restrict__ A_log)
{
    const int bc = blockIdx.x;
    const int b = bc / NC, c = bc - b*NC;
    const int d = threadIdx.x;
    const int l0 = c * CL;

    __shared__ __align__(16) float sF[CL][48];   // delta_r, Bf, Bb
    __shared__ __align__(16) float sBb[CL][16];  // mirror xb-proj

    for (int i = d; i < CL*48; i += 256) {
        const int r = i / 48, col = i - r*48;
        sF[r][col] = g_P80[(size_t)(b*L_ + l0 + r)*NP + col];
    }
    for (int i = d; i < CL*16; i += 256) {
        const int r = i >> 4, col = i & 15;
        sBb[r][col] = g_P80[(size_t)(b*L_ + (L_ - 1 - (l0 + r)))*NP + 64 + col];
    }
    __syncthreads();

    float wdt[R_];
    #pragma unroll
    for (int q = 0; q < R_; ++q) wdt[q] = __ldg(Wdt + d*R_ + q);
    const float bv = bdt[d];
    bool fast;
    const float a0 = check_A(A_log, d, fast);

    const float* x_ptr  = x + (b*L_ + l0)*D_ + d;
    const float* xr_ptr = x + (b*L_ + (L_ - 1 - l0))*D_ + d;
    float* Pp = g_P + ((b*NC + c)*N_)*D_ + d;
    float* Hp = g_H + ((b*NC + c)*N_)*D_ + d;

    if (fast) {
        ull h2[8];
        #pragma unroll
        for (int k = 0; k < 8; ++k) h2[k] = 0ull;
        float p1 = 1.f;

        #pragma unroll
        for (int t0 = 0; t0 < CL; t0 += 4) {
            float xv[4], xr[4];
            #pragma unroll
            for (int i = 0; i < 4; ++i) {
                xv[i] = x_ptr [(t0+i)*D_];
                xr[i] = xr_ptr[-(t0+i)*D_];
            }
            #pragma unroll
            for (int i = 0; i < 4; ++i) {
                const int t = t0 + i;
                const float2* qa = reinterpret_cast<const float2*>(&sF[t][0]);
                const float2* qb = reinterpret_cast<const float2*>(&sBb[t][0]);
                float s0 = bv, s1 = 0.f, u0 = bv, u1 = 0.f;
                #pragma unroll
                for (int q = 0; q < 8; ++q) {
                    const float2 av = qa[q], bw = qb[q];
                    s0 = fmaf(av.x, wdt[2*q],   s0);
                    s1 = fmaf(av.y, wdt[2*q+1], s1);
                    u0 = fmaf(bw.x, wdt[2*q],   u0);
                    u1 = fmaf(bw.y, wdt[2*q+1], u1);
                }
                const float dl  = softplusf(s0 + s1);
                const float dlb = softplusf(u0 + u1);

                const float e1 = __expf(dl * a0);
                const float e1sq = e1 * e1;
                ull e = pack2(e1, e1sq);
                const ull estep = pack2(e1sq, e1sq);
                const float c1 = dl * xv[i], c2 = dlb * xr[i];
                const ull c1p = pack2(c1, c1);
                const ull c2p = pack2(c2, c2);
                const ull* Bf2 = reinterpret_cast<const ull*>(&sF[t][16]);
                const ull* Bb2 = reinterpret_cast<const ull*>(&sF[t][32]);
                #pragma unroll
                for (int k = 0; k < 8; ++k) {
                    const ull du = fma2(c1p, Bf2[k], mul2(c2p, Bb2[k]));
                    h2[k] = fma2(e, h2[k], du);
                    if (k < 7) e = mul2(e, estep);
                }
                p1 *= e1;
            }
        }
        ull pw2[8]; powers16_p2(p1, pw2);
        #pragma unroll
        for (int k = 0; k < 8; ++k) {
            float plo, phi; unpack2(pw2[k], plo, phi);
            float hlo, hhi; unpack2(h2[k], hlo, hhi);
            Pp[(2*k  )*D_] = plo;  Pp[(2*k+1)*D_] = phi;
            Hp[(2*k  )*D_] = hlo;  Hp[(2*k+1)*D_] = hhi;
        }
    } else {
        float h[N_], a[N_], p[N_];
        #pragma unroll
        for (int n = 0; n < N_; ++n) {
            a[n] = -__expf(__ldg(A_log + d*N_ + n));
            p[n] = 1.f;
            h[n] = 0.f;
        }
        for (int t = 0; t < CL; ++t) {
            float s = bv, sb = bv;
            #pragma unroll
            for (int q = 0; q < R_; ++q) {
                s  = fmaf(sF[t][q],  wdt[q], s);
                sb = fmaf(sBb[t][q], wdt[q], sb);
            }
            const float dl  = softplusf(s);
            const float dlb = softplusf(sb);
            const float xv = x_ptr[t*D_];
            const float xr = xr_ptr[-t*D_];
            const float c1 = dl*xv, c2 = dlb*xr;
            #pragma unroll
            for (int n = 0; n < N_; ++n) {
                const float e = __expf(dl * a[n]);
                h[n] = fmaf(e, h[n], fmaf(c1, sF[t][16+n], c2 * sF[t][32+n]));
                p[n] *= e;
            }
        }
        #pragma unroll
        for (int n = 0; n < N_; ++n) { Pp[n*D_] = p[n]; Hp[n*D_] = h[n]; }
    }
}

// ---------------------------------------------------------------------------
// Kernel 3: combine — 8 segments x 8 chunks, 1024 threads (unchanged).
// ---------------------------------------------------------------------------
__global__ __launch_bounds__(1024) void combine_kernel()
{
    const int bn = blockIdx.x;
    const int b = bn >> 4;
    const int n = bn & 15;
    const int seg = threadIdx.x >> 7;
    const int dp  = threadIdx.x & 127;

    __shared__ ull sP[NSEG][128];
    __shared__ ull sH[NSEG][128];

    const ull* P2 = reinterpret_cast<const ull*>(g_P);
    const ull* H2 = reinterpret_cast<const ull*>(g_H);
    ull* hs2 = reinterpret_cast<ull*>(g_hs);

    const int c0 = seg * SEGC;
    #define CIDX(c) ((((b*NC + (c))*N_) + n)*128 + dp)

    ull Pc = pack2(1.f, 1.f), Hc = 0ull;
    #pragma unroll
    for (int i = 0; i < SEGC; ++i) {
        const int idx = CIDX(c0 + i);
        const ull p = P2[idx];
        Pc = mul2(p, Pc);
        Hc = fma2(p, Hc, H2[idx]);
    }
    sP[seg][dp] = Pc;
    sH[seg][dp] = Hc;
    __syncthreads();

    ull h = 0ull;
    #pragma unroll
    for (int t = 0; t < NSEG-1; ++t)
        if (t < seg) h = fma2(sP[t][dp], h, sH[t][dp]);

    #pragma unroll
    for (int i = 0; i < SEGC; ++i) {
        const int idx = CIDX(c0 + i);
        hs2[idx] = h;
        h = fma2(P2[idx], h, H2[idx]);
    }
    #undef CIDX
}

// ---------------------------------------------------------------------------
// Kernel 4: scan2 — recurrence seeded with carried h0 = g_hs; exact h_t,
// y = h·C + skip; writes packed y16 directly. No correction pass needed.
// ---------------------------------------------------------------------------
__global__ __launch_bounds__(256) void scan2_kernel(
    const float* __restrict__ x, const float* __restrict__ Wdt,
    const float* __restrict__ bdt, const float* __restrict__ A_log,
    const float* __restrict__ Dskip)
{
    const int bc = blockIdx.x;
    const int b = bc / NC, c = bc - b*NC;
    const int d = threadIdx.x;
    const int l0 = c * CL;

    __shared__ __align__(16) float sF[CL][64];   // delta_r, Bf, Bb, C
    __shared__ __align__(16) float sBb[CL][16];

    for (int i = d; i < CL*64; i += 256) {
        const int r = i >> 6, col = i & 63;
        sF[r][col] = g_P80[(size_t)(b*L_ + l0 + r)*NP + col];
    }
    for (int i = d; i < CL*16; i += 256) {
        const int r = i >> 4, col = i & 15;
        sBb[r][col] = g_P80[(size_t)(b*L_ + (L_ - 1 - (l0 + r)))*NP + 64 + col];
    }
    __syncthreads();

    float wdt[R_];
    #pragma unroll
    for (int q = 0; q < R_; ++q) wdt[q] = __ldg(Wdt + d*R_ + q);
    const float bv  = bdt[d];
    const float dsk = Dskip[d];
    bool fast;
    const float a0 = check_A(A_log, d, fast);

    const float* x_ptr  = x + (b*L_ + l0)*D_ + d;
    const float* xr_ptr = x + (b*L_ + (L_ - 1 - l0))*D_ + d;
    uint32_t* y16_ptr   = g_y16 + (b*L_ + l0)*D_ + d;

    if (fast) {
        ull h2[8];
        #pragma unroll
        for (int k = 0; k < 8; ++k) {
            const float qlo = g_hs[((b*NC + c)*N_ + 2*k  )*D_ + d];
            const float qhi = g_hs[((b*NC + c)*N_ + 2*k+1)*D_ + d];
            h2[k] = pack2(qlo, qhi);
        }

        #pragma unroll
        for (int t0 = 0; t0 < CL; t0 += 4) {
            float xv[4], xr[4];
            #pragma unroll
            for (int i = 0; i < 4; ++i) {
                xv[i] = x_ptr [(t0+i)*D_];
                xr[i] = xr_ptr[-(t0+i)*D_];
            }
            #pragma unroll
            for (int i = 0; i < 4; ++i) {
                const int t = t0 + i;
                const float2* qa = reinterpret_cast<const float2*>(&sF[t][0]);
                const float2* qb = reinterpret_cast<const float2*>(&sBb[t][0]);
                float s0 = bv, s1 = 0.f, u0 = bv, u1 = 0.f;
                #pragma unroll
                for (int q = 0; q < 8; ++q) {
                    const float2 av = qa[q], bw = qb[q];
                    s0 = fmaf(av.x, wdt[2*q],   s0);
                    s1 = fmaf(av.y, wdt[2*q+1], s1);
                    u0 = fmaf(bw.x, wdt[2*q],   u0);
                    u1 = fmaf(bw.y, wdt[2*q+1], u1);
                }
                const float dl  = softplusf(s0 + s1);
                const float dlb = softplusf(u0 + u1);

                const float e1 = __expf(dl * a0);
                const float e1sq = e1 * e1;
                ull e = pack2(e1, e1sq);
                const ull estep = pack2(e1sq, e1sq);
                const float c1 = dl * xv[i], c2 = dlb * xr[i];
                const ull c1p = pack2(c1, c1);
                const ull c2p = pack2(c2, c2);
                ull y2 = 0ull;
                const ull* Bf2 = reinterpret_cast<const ull*>(&sF[t][16]);
                const ull* Bb2 = reinterpret_cast<const ull*>(&sF[t][32]);
                const ull* C2  = reinterpret_cast<const ull*>(&sF[t][48]);
                #pragma unroll
                for (int k = 0; k < 8; ++k) {
                    const ull du = fma2(c1p, Bf2[k], mul2(c2p, Bb2[k]));
                    h2[k] = fma2(e, h2[k], du);
                    y2    = fma2(h2[k], C2[k], y2);
                    if (k < 7) e = mul2(e, estep);
                }
                float ylo, yhi; unpack2(y2, ylo, yhi);
                y16_ptr[t*D_] = pack_hilo(fmaf(xv[i] + xr[i], dsk, ylo + yhi));
            }
        }
    } else {
        float h[N_], a[N_];
        #pragma unroll
        for (int n = 0; n < N_; ++n) {
            a[n] = -__expf(__ldg(A_log + d*N_ + n));
            h[n] = g_hs[((b*NC + c)*N_ + n)*D_ + d];
        }
        for (int t = 0; t < CL; ++t) {
            float s = bv, sb = bv;
            #pragma unroll
            for (int q = 0; q < R_; ++q) {
                s  = fmaf(sF[t][q],  wdt[q], s);
                sb = fmaf(sBb[t][q], wdt[q], sb);
            }
            const float dl  = softplusf(s);
            const float dlb = softplusf(sb);
            const float xv = x_ptr[t*D_];
            const float xr = xr_ptr[-t*D_];
            const float c1 = dl*xv, c2 = dlb*xr;
            float y = 0.f;
            #pragma unroll
            for (int n = 0; n < N_; ++n) {
                const float e = __expf(dl * a[n]);
                h[n] = fmaf(e, h[n], fmaf(c1, sF[t][16+n], c2 * sF[t][32+n]));
                y    = fmaf(h[n], sF[t][48+n], y);
            }
            y16_ptr[t*D_] = pack_hilo(fmaf(xv + xr, dsk, y));
        }
    }
}

// ---------------------------------------------------------------------------
// Kernel 5: out GEMM — pipelined split-bf16 (unchanged from R15).
// ---------------------------------------------------------------------------
__global__ __launch_bounds__(256) void gemm_mma_kernel(float* __restrict__ out)
{
    extern __shared__ __nv_bfloat16 sm[];
    __nv_bfloat16* sA_hi = sm;
    __nv_bfloat16* sA_lo = sm + 128*GP;
    __nv_bfloat16* sB_hi = sm + 2*128*GP;
    __nv_bfloat16* sB_lo = sm + 3*128*GP;

    const int tid  = threadIdx.x;
    const int wid  = tid >> 5;
    const int lane = tid & 31;
    const int gid  = lane >> 2;
    const int t4   = lane & 3;

    const int j0 = blockIdx.x * 128;
    const int m0 = blockIdx.y * 128;
    const int wm = (wid >> 2) * 64;
    const int wn = (wid & 3) * 32;

    float acc[4][4][4];
    #pragma unroll
    for (int i = 0; i < 4; ++i)
        #pragma unroll
        for (int j = 0; j < 4; ++j)
            #pragma unroll
            for (int q = 0; q < 4; ++q) acc[i][j][q] = 0.f;

    const int lrow = tid >> 5;
    const int lpc  = tid & 31;

    uint2 pa[16], pb[16];
    #pragma unroll
    for (int rr = 0; rr < 16; ++rr) {
        const int row = lrow + rr*8;
        pa[rr] = *reinterpret_cast<const uint2*>(g_y16 + (m0 + row)*D_ + lpc*2);
        pb[rr] = *reinterpret_cast<const uint2*>(g_W16 + (j0 + row)*D_ + lpc*2);
    }

    for (int kc = 0; kc < 256; kc += 64) {
        #pragma unroll
        for (int rr = 0; rr < 16; ++rr) {
            const int row = lrow + rr*8;
            const int soff = row*GP + lpc*2;
            *reinterpret_cast<uint32_t*>(sA_hi + soff) = __byte_perm(pa[rr].x, pa[rr].y, 0x5410);
            *reinterpret_cast<uint32_t*>(sA_lo + soff) = __byte_perm(pa[rr].x, pa[rr].y, 0x7632);
            *reinterpret_cast<uint32_t*>(sB_hi + soff) = __byte_perm(pb[rr].x, pb[rr].y, 0x5410);
            *reinterpret_cast<uint32_t*>(sB_lo + soff) = __byte_perm(pb[rr].x, pb[rr].y, 0x7632);
        }
        __syncthreads();

        if (kc < 192) {
            #pragma unroll
            for (int rr = 0; rr < 16; ++rr) {
                const int row = lrow + rr*8;
                pa[rr] = *reinterpret_cast<const uint2*>(
                    g_y16 + (m0 + row)*D_ + kc + 64 + lpc*2);
                pb[rr] = *reinterpret_cast<const uint2*>(
                    g_W16 + (j0 + row)*D_ + kc + 64 + lpc*2);
            }
        }

        #pragma unroll
        for (int ks = 0; ks < 4; ++ks) {
            const int k0 = ks*16;
            uint32_t a_hi[4][4], a_lo[4][4], b_hi[4][2], b_lo[4][2];
            #pragma unroll
            for (int mf = 0; mf < 4; ++mf) {
                const int r0 = wm + mf*16 + gid;
                const int c0 = k0 + t4*2;
                a_hi[mf][0] = *reinterpret_cast<const uint32_t*>(sA_hi + (r0    )*GP + c0    );
                a_hi[mf][1] = *reinterpret_cast<const uint32_t*>(sA_hi + (r0 + 8)*GP + c0    );
                a_hi[mf][2] = *reinterpret_cast<const uint32_t*>(sA_hi + (r0    )*GP + c0 + 8);
                a_hi[mf][3] = *reinterpret_cast<const uint32_t*>(sA_hi + (r0 + 8)*GP + c0 + 8);
                a_lo[mf][0] = *reinterpret_cast<const uint32_t*>(sA_lo + (r0    )*GP + c0    );
                a_lo[mf][1] = *reinterpret_cast<const uint32_t*>(sA_lo + (r0 + 8)*GP + c0    );
                a_lo[mf][2] = *reinterpret_cast<const uint32_t*>(sA_lo + (r0    )*GP + c0 + 8);
                a_lo[mf][3] = *reinterpret_cast<const uint32_t*>(sA_lo + (r0 + 8)*GP + c0 + 8);
            }
            #pragma unroll
            for (int nf = 0; nf < 4; ++nf) {
                const int nr = wn + nf*8 + gid;
                const int c0 = k0 + t4*2;
                b_hi[nf][0] = *reinterpret_cast<const uint32_t*>(sB_hi + nr*GP + c0    );
                b_hi[nf][1] = *reinterpret_cast<const uint32_t*>(sB_hi + nr*GP + c0 + 8);
                b_lo[nf][0] = *reinterpret_cast<const uint32_t*>(sB_lo + nr*GP + c0    );
                b_lo[nf][1] = *reinterpret_cast<const uint32_t*>(sB_lo + nr*GP + c0 + 8);
            }
            #pragma unroll
            for (int mf = 0; mf < 4; ++mf)
                #pragma unroll
                for (int nf = 0; nf < 4; ++nf) {
                    mma_bf16(acc[mf][nf], a_hi[mf], b_hi[nf]);
                    mma_bf16(acc[mf][nf], a_hi[mf], b_lo[nf]);
                    mma_bf16(acc[mf][nf], a_lo[mf], b_hi[nf]);
                }
        }
        __syncthreads();
    }

    #pragma unroll
    for (int mf = 0; mf < 4; ++mf) {
        const int mrow = m0 + wm + mf*16 + gid;
        #pragma unroll
        for (int nf = 0; nf < 4; ++nf) {
            const int ncol = j0 + wn + nf*8 + t4*2;
            *reinterpret_cast<float2*>(out + (size_t)mrow*D_ + ncol) =
                make_float2(acc[mf][nf][0], acc[mf][nf][1]);
            *reinterpret_cast<float2*>(out + (size_t)(mrow + 8)*D_ + ncol) =
                make_float2(acc[mf][nf][2], acc[mf][nf][3]);
        }
    }
}

// ---------------------------------------------------------------------------
extern "C" void kernel_launch(void* const* d_in, const int* in_sizes, int n_in,
                              void* d_out, int out_size)
{
    const float* x     = (const float*)d_in[0];
    const float* Wxp   = (const float*)d_in[1];
    const float* Wxb   = (const float*)d_in[2];
    const float* Wdt   = (const float*)d_in[3];
    const float* bdt   = (const float*)d_in[4];
    const float* A_log = (const float*)d_in[5];
    const float* Dskip = (const float*)d_in[6];
    const float* Wout  = (const float*)d_in[7];
    float* out = (float*)d_out;

    const int GEMM_SMEM = 4 * 128 * GP * (int)sizeof(__nv_bfloat16);  // 73728 B
    cudaFuncSetAttribute(gemm_mma_kernel,
                         cudaFuncAttributeMaxDynamicSharedMemorySize, GEMM_SMEM);
    cudaFuncSetAttribute(projgemm_kernel,
                         cudaFuncAttributeMaxDynamicSharedMemorySize, GEMM_SMEM);

    projgemm_kernel<<<dim3(1, 128), 256, GEMM_SMEM>>>(x, Wxp, Wxb, Wout);
    scan1_kernel   <<<B_*NC, 256>>>(x, Wdt, bdt, A_log);
    combine_kernel <<<B_*N_, 1024>>>();
    scan2_kernel   <<<B_*NC, 256>>>(x, Wdt, bdt, A_log, Dskip);
    gemm_mma_kernel<<<dim3(2, 128), 256, GEMM_SMEM>>>(out);
}

// round 17
// speedup vs baseline: 1.1411x; 1.1411x over previous
#include <cuda_runtime.h>
#include <cuda_bf16.h>
#include <math.h>
#include <stdint.h>

#define B_    8
#define L_    2048
#define D_    256
#define N_    16
#define R_    16
#define CL    32          // scan chunk length
#define NC    (L_/CL)     // 64 chunks
#define NSEG  8           // combine segments
#define SEGC  (NC/NSEG)   // 8 chunks per combine segment
#define NP    80          // projection outputs per row

typedef unsigned long long ull;

// ---------------- scratch (device globals) ----------------
__device__ float    g_P80    [B_*L_*NP];
__device__ float    g_delta  [B_*L_*D_];      // slow-path only
__device__ float    g_pc     [B_*L_*D_];
__device__ float    g_P      [B_*NC*N_*D_];
__device__ float    g_H      [B_*NC*N_*D_];
__device__ float    g_hs     [B_*NC*N_*D_];
__device__ float    g_y      [B_*L_*D_];
__device__ uint32_t g_y16    [B_*L_*D_];
__device__ uint32_t g_W16    [D_*D_];

// FAST softplus (MUFU EX2/LG2 — library log1pf cost ~70 µs, R13->R14)
__device__ __forceinline__ float softplusf(float v) {
    return v > 20.0f ? v : __logf(1.0f + __expf(v));
}

__device__ __forceinline__ uint32_t pack_hilo(float v) {
    __nv_bfloat16 h = __float2bfloat16(v);
    __nv_bfloat16 l = __float2bfloat16(v - __bfloat162float(h));
    return (uint32_t)__bfloat16_as_ushort(h) |
           ((uint32_t)__bfloat16_as_ushort(l) << 16);
}

// ---------------- packed f32x2 helpers ----------------
__device__ __forceinline__ ull pack2(float lo, float hi) {
    ull r;
    asm("mov.b64 %0, {%1, %2};" : "=l"(r) : "f"(lo), "f"(hi));
    return r;
}
__device__ __forceinline__ void unpack2(ull v, float& lo, float& hi) {
    asm("mov.b64 {%0, %1}, %2;" : "=f"(lo), "=f"(hi) : "l"(v));
}
__device__ __forceinline__ ull mul2(ull a, ull b) {
    ull d;
    asm("mul.rn.f32x2 %0, %1, %2;" : "=l"(d) : "l"(a), "l"(b));
    return d;
}
__device__ __forceinline__ ull fma2(ull a, ull b, ull c) {
    ull d;
    asm("fma.rn.f32x2 %0, %1, %2, %3;" : "=l"(d) : "l"(a), "l"(b), "l"(c));
    return d;
}
__device__ __forceinline__ void powers16_p2(float p1, ull e2[8]) {
    const float p1sq = p1 * p1;
    e2[0] = pack2(p1, p1sq);
    const ull pstep = pack2(p1sq, p1sq);
    #pragma unroll
    for (int k = 1; k < 8; ++k) e2[k] = mul2(e2[k-1], pstep);
}

__device__ __forceinline__ float check_A(const float* __restrict__ A_log,
                                         int d, bool& fast) {
    float a0 = -__expf(__ldg(A_log + d*N_));
    fast = true;
    #pragma unroll
    for (int n = 1; n < N_; ++n) {
        float an = -__expf(__ldg(A_log + d*N_ + n));
        fast = fast && (fabsf(an - a0*(float)(n+1)) <= 1e-4f*(float)(n+1));
    }
    return a0;
}

// ---------------------------------------------------------------------------
// Kernel 1: projgemm — P80 = x @ [Wxp;Wxb;0]^T via mma.sync bf16 split.
// M split into 64-row tiles (grid 256 > 148 SMs); warp tile 32x32.
// Also packs W_out (1 elem/thread over 256 blocks). W rows converted inline.
// ---------------------------------------------------------------------------
#define GP 72   // smem pitch in bf16 elements

__device__ __forceinline__ void mma_bf16(float dd[4],
                                         const uint32_t a[4],
                                         const uint32_t b[2]) {
    asm volatile(
        "mma.sync.aligned.m16n8k16.row.col.f32.bf16.bf16.f32 "
        "{%0,%1,%2,%3}, {%4,%5,%6,%7}, {%8,%9}, {%0,%1,%2,%3};"
        : "+f"(dd[0]), "+f"(dd[1]), "+f"(dd[2]), "+f"(dd[3])
        : "r"(a[0]), "r"(a[1]), "r"(a[2]), "r"(a[3]), "r"(b[0]), "r"(b[1]));
}

__device__ __forceinline__ float2 wall_row(const float* __restrict__ Wxp,
                                           const float* __restrict__ Wxb,
                                           int row, int off) {
    if (row < 64)  return *reinterpret_cast<const float2*>(Wxp + row*D_ + off);
    if (row < 80)  return *reinterpret_cast<const float2*>(Wxb + (row-64)*D_ + off);
    return make_float2(0.f, 0.f);
}

__device__ __forceinline__ void cvt_store_pair(__nv_bfloat16* hi_p,
                                               __nv_bfloat16* lo_p, float2 v) {
    __nv_bfloat16 hx = __float2bfloat16(v.x);
    __nv_bfloat16 hy = __float2bfloat16(v.y);
    __nv_bfloat16 lx = __float2bfloat16(v.x - __bfloat162float(hx));
    __nv_bfloat16 ly = __float2bfloat16(v.y - __bfloat162float(hy));
    *reinterpret_cast<__nv_bfloat162*>(hi_p) = __nv_bfloat162(hx, hy);
    *reinterpret_cast<__nv_bfloat162*>(lo_p) = __nv_bfloat162(lx, ly);
}

__global__ __launch_bounds__(256) void projgemm_kernel(
    const float* __restrict__ x,   const float* __restrict__ Wxp,
    const float* __restrict__ Wxb, const float* __restrict__ Wout)
{
    extern __shared__ __nv_bfloat16 sm[];
    __nv_bfloat16* sA_hi = sm;                  // [64][GP]
    __nv_bfloat16* sA_lo = sm + 64*GP;
    __nv_bfloat16* sB_hi = sm + 2*64*GP;        // [128][GP]
    __nv_bfloat16* sB_lo = sm + 2*64*GP + 128*GP;

    const int tid  = threadIdx.x;
    const int wid  = tid >> 5;
    const int lane = tid & 31;
    const int gid  = lane >> 2;
    const int t4   = lane & 3;

    // side job: pack W_out (256 blocks x 256 threads = 65536 elements)
    {
        const int gidx = blockIdx.y*256 + tid;
        g_W16[gidx] = pack_hilo(Wout[gidx]);
    }

    const int m0 = blockIdx.y * 64;
    const int wm = (wid >> 2) * 32;
    const int wn = (wid & 3) * 32;

    float acc[2][4][4];
    #pragma unroll
    for (int i = 0; i < 2; ++i)
        #pragma unroll
        for (int j = 0; j < 4; ++j)
            #pragma unroll
            for (int q = 0; q < 4; ++q) acc[i][j][q] = 0.f;

    const int lrow = tid >> 5;   // 0..7
    const int lpc  = tid & 31;

    for (int kc = 0; kc < 256; kc += 64) {
        // A tile: 64 rows
        #pragma unroll
        for (int rr = 0; rr < 8; ++rr) {
            const int row = lrow + rr*8;
            const int soff = row*GP + lpc*2;
            const float2 va = *reinterpret_cast<const float2*>(
                x + (size_t)(m0 + row)*D_ + kc + lpc*2);
            cvt_store_pair(sA_hi + soff, sA_lo + soff, va);
        }
        // B tile: 128 rows (zero-padded weight stack)
        #pragma unroll
        for (int rr = 0; rr < 16; ++rr) {
            const int row = lrow + rr*8;
            const int soff = row*GP + lpc*2;
            const float2 vb = wall_row(Wxp, Wxb, row, kc + lpc*2);
            cvt_store_pair(sB_hi + soff, sB_lo + soff, vb);
        }
        __syncthreads();

        #pragma unroll
        for (int ks = 0; ks < 4; ++ks) {
            const int k0 = ks*16;
            uint32_t a_hi[2][4], a_lo[2][4], b_hi[4][2], b_lo[4][2];
            #pragma unroll
            for (int mf = 0; mf < 2; ++mf) {
                const int r0 = wm + mf*16 + gid;
                const int c0 = k0 + t4*2;
                a_hi[mf][0] = *reinterpret_cast<const uint32_t*>(sA_hi + (r0    )*GP + c0    );
                a_hi[mf][1] = *reinterpret_cast<const uint32_t*>(sA_hi + (r0 + 8)*GP + c0    );
                a_hi[mf][2] = *reinterpret_cast<const uint32_t*>(sA_hi + (r0    )*GP + c0 + 8);
                a_hi[mf][3] = *reinterpret_cast<const uint32_t*>(sA_hi + (r0 + 8)*GP + c0 + 8);
                a_lo[mf][0] = *reinterpret_cast<const uint32_t*>(sA_lo + (r0    )*GP + c0    );
                a_lo[mf][1] = *reinterpret_cast<const uint32_t*>(sA_lo + (r0 + 8)*GP + c0    );
                a_lo[mf][2] = *reinterpret_cast<const uint32_t*>(sA_lo + (r0    )*GP + c0 + 8);
                a_lo[mf][3] = *reinterpret_cast<const uint32_t*>(sA_lo + (r0 + 8)*GP + c0 + 8);
            }
            #pragma unroll
            for (int nf = 0; nf < 4; ++nf) {
                const int nr = wn + nf*8 + gid;
                const int c0 = k0 + t4*2;
                b_hi[nf][0] = *reinterpret_cast<const uint32_t*>(sB_hi + nr*GP + c0    );
                b_hi[nf][1] = *reinterpret_cast<const uint32_t*>(sB_hi + nr*GP + c0 + 8);
                b_lo[nf][0] = *reinterpret_cast<const uint32_t*>(sB_lo + nr*GP + c0    );
                b_lo[nf][1] = *reinterpret_cast<const uint32_t*>(sB_lo + nr*GP + c0 + 8);
            }
            #pragma unroll
            for (int mf = 0; mf < 2; ++mf)
                #pragma unroll
                for (int nf = 0; nf < 4; ++nf) {
                    mma_bf16(acc[mf][nf], a_hi[mf], b_hi[nf]);
                    mma_bf16(acc[mf][nf], a_hi[mf], b_lo[nf]);
                    mma_bf16(acc[mf][nf], a_lo[mf], b_hi[nf]);
                }
        }
        __syncthreads();
    }

    #pragma unroll
    for (int mf = 0; mf < 2; ++mf) {
        const int mrow = m0 + wm + mf*16 + gid;
        #pragma unroll
        for (int nf = 0; nf < 4; ++nf) {
            const int ncol = wn + nf*8 + t4*2;
            if (ncol < NP) {
                *reinterpret_cast<float2*>(g_P80 + (size_t)mrow*NP + ncol) =
                    make_float2(acc[mf][nf][0], acc[mf][nf][1]);
                *reinterpret_cast<float2*>(g_P80 + (size_t)(mrow + 8)*NP + ncol) =
                    make_float2(acc[mf][nf][2], acc[mf][nf][3]);
            }
        }
    }
}

// ---------------------------------------------------------------------------
// Kernel 2: scan — one expensive pass: recurrence from h=0, emits y_local,
// pcum, P, H (R15 structure, known good).
// ---------------------------------------------------------------------------
__global__ __launch_bounds__(256) void scan_kernel(
    const float* __restrict__ x, const float* __restrict__ Wdt,
    const float* __restrict__ bdt, const float* __restrict__ A_log,
    const float* __restrict__ Dskip)
{
    const int bc = blockIdx.x;
    const int b = bc / NC, c = bc - b*NC;
    const int d = threadIdx.x;
    const int l0 = c * CL;

    __shared__ __align__(16) float sF[CL][64];
    __shared__ __align__(16) float sBb[CL][16];

    for (int i = d; i < CL*64; i += 256) {
        const int r = i >> 6, col = i & 63;
        sF[r][col] = g_P80[(size_t)(b*L_ + l0 + r)*NP + col];
    }
    for (int i = d; i < CL*16; i += 256) {
        const int r = i >> 4, col = i & 15;
        sBb[r][col] = g_P80[(size_t)(b*L_ + (L_ - 1 - (l0 + r)))*NP + 64 + col];
    }
    __syncthreads();

    float wdt[R_];
    #pragma unroll
    for (int q = 0; q < R_; ++q) wdt[q] = __ldg(Wdt + d*R_ + q);
    const float bv  = bdt[d];
    const float dsk = Dskip[d];
    bool fast;
    const float a0 = check_A(A_log, d, fast);

    const float* x_ptr  = x + (b*L_ + l0)*D_ + d;
    const float* xr_ptr = x + (b*L_ + (L_ - 1 - l0))*D_ + d;
    float* y_ptr  = g_y  + (b*L_ + l0)*D_ + d;
    float* pc_ptr = g_pc + (b*L_ + l0)*D_ + d;
    float* Pp = g_P + ((b*NC + c)*N_)*D_ + d;
    float* Hp = g_H + ((b*NC + c)*N_)*D_ + d;

    if (fast) {
        ull h2[8];
        #pragma unroll
        for (int k = 0; k < 8; ++k) h2[k] = 0ull;
        float p1 = 1.f;

        #pragma unroll
        for (int t0 = 0; t0 < CL; t0 += 4) {
            float xv[4], xr[4];
            #pragma unroll
            for (int i = 0; i < 4; ++i) {
                xv[i] = x_ptr [(t0+i)*D_];
                xr[i] = xr_ptr[-(t0+i)*D_];
            }
            #pragma unroll
            for (int i = 0; i < 4; ++i) {
                const int t = t0 + i;
                const float2* qa = reinterpret_cast<const float2*>(&sF[t][0]);
                const float2* qb = reinterpret_cast<const float2*>(&sBb[t][0]);
                float s0 = bv, s1 = 0.f, u0 = bv, u1 = 0.f;
                #pragma unroll
                for (int q = 0; q < 8; ++q) {
                    const float2 av = qa[q], bw = qb[q];
                    s0 = fmaf(av.x, wdt[2*q],   s0);
                    s1 = fmaf(av.y, wdt[2*q+1], s1);
                    u0 = fmaf(bw.x, wdt[2*q],   u0);
                    u1 = fmaf(bw.y, wdt[2*q+1], u1);
                }
                const float dl  = softplusf(s0 + s1);
                const float dlb = softplusf(u0 + u1);

                const float e1 = __expf(dl * a0);
                const float e1sq = e1 * e1;
                ull e = pack2(e1, e1sq);
                const ull estep = pack2(e1sq, e1sq);
                const float c1 = dl * xv[i], c2 = dlb * xr[i];
                const ull c1p = pack2(c1, c1);
                const ull c2p = pack2(c2, c2);
                ull y2 = 0ull;
                const ull* Bf2 = reinterpret_cast<const ull*>(&sF[t][16]);
                const ull* Bb2 = reinterpret_cast<const ull*>(&sF[t][32]);
                const ull* C2  = reinterpret_cast<const ull*>(&sF[t][48]);
                #pragma unroll
                for (int k = 0; k < 8; ++k) {
                    const ull du = fma2(c1p, Bf2[k], mul2(c2p, Bb2[k]));
                    h2[k] = fma2(e, h2[k], du);
                    y2    = fma2(h2[k], C2[k], y2);
                    if (k < 7) e = mul2(e, estep);
                }
                p1 *= e1;
                float ylo, yhi; unpack2(y2, ylo, yhi);
                y_ptr [t*D_] = fmaf(xv[i] + xr[i], dsk, ylo + yhi);
                pc_ptr[t*D_] = p1;
            }
        }
        ull pw2[8]; powers16_p2(p1, pw2);
        #pragma unroll
        for (int k = 0; k < 8; ++k) {
            float plo, phi; unpack2(pw2[k], plo, phi);
            float hlo, hhi; unpack2(h2[k], hlo, hhi);
            Pp[(2*k  )*D_] = plo;  Pp[(2*k+1)*D_] = phi;
            Hp[(2*k  )*D_] = hlo;  Hp[(2*k+1)*D_] = hhi;
        }
    } else {
        float h[N_], a[N_], p[N_];
        #pragma unroll
        for (int n = 0; n < N_; ++n) {
            a[n] = -__expf(__ldg(A_log + d*N_ + n));
            p[n] = 1.f;
            h[n] = 0.f;
        }
        for (int t = 0; t < CL; ++t) {
            float s = bv, sb = bv;
            #pragma unroll
            for (int q = 0; q < R_; ++q) {
                s  = fmaf(sF[t][q],  wdt[q], s);
                sb = fmaf(sBb[t][q], wdt[q], sb);
            }
            const float dl  = softplusf(s);
            const float dlb = softplusf(sb);
            g_delta[(b*L_ + l0 + t)*D_ + d] = dl;
            const float xv = x_ptr[t*D_];
            const float xr = xr_ptr[-t*D_];
            const float c1 = dl*xv, c2 = dlb*xr;
            float y = 0.f;
            #pragma unroll
            for (int n = 0; n < N_; ++n) {
                const float e = __expf(dl * a[n]);
                h[n] = fmaf(e, h[n], fmaf(c1, sF[t][16+n], c2 * sF[t][32+n]));
                y    = fmaf(h[n], sF[t][48+n], y);
                p[n] *= e;
            }
            y_ptr[t*D_] = fmaf(xv + xr, dsk, y);
        }
        #pragma unroll
        for (int n = 0; n < N_; ++n) { Pp[n*D_] = p[n]; Hp[n*D_] = h[n]; }
    }
}

// ---------------------------------------------------------------------------
// Kernel 3: combine — 8 segments x 8 chunks, 1024 threads (unchanged).
// ---------------------------------------------------------------------------
__global__ __launch_bounds__(1024) void combine_kernel()
{
    const int bn = blockIdx.x;
    const int b = bn >> 4;
    const int n = bn & 15;
    const int seg = threadIdx.x >> 7;
    const int dp  = threadIdx.x & 127;

    __shared__ ull sP[NSEG][128];
    __shared__ ull sH[NSEG][128];

    const ull* P2 = reinterpret_cast<const ull*>(g_P);
    const ull* H2 = reinterpret_cast<const ull*>(g_H);
    ull* hs2 = reinterpret_cast<ull*>(g_hs);

    const int c0 = seg * SEGC;
    #define CIDX(c) ((((b*NC + (c))*N_) + n)*128 + dp)

    ull Pc = pack2(1.f, 1.f), Hc = 0ull;
    #pragma unroll
    for (int i = 0; i < SEGC; ++i) {
        const int idx = CIDX(c0 + i);
        const ull p = P2[idx];
        Pc = mul2(p, Pc);
        Hc = fma2(p, Hc, H2[idx]);
    }
    sP[seg][dp] = Pc;
    sH[seg][dp] = Hc;
    __syncthreads();

    ull h = 0ull;
    #pragma unroll
    for (int t = 0; t < NSEG-1; ++t)
        if (t < seg) h = fma2(sP[t][dp], h, sH[t][dp]);

    #pragma unroll
    for (int i = 0; i < SEGC; ++i) {
        const int idx = CIDX(c0 + i);
        hs2[idx] = h;
        h = fma2(P2[idx], h, H2[idx]);
    }
    #undef CIDX
}

// ---------------------------------------------------------------------------
// Kernel 4: correct2 — y += pcum^n * hs * C; emits packed y16 (R15 version).
// ---------------------------------------------------------------------------
__global__ __launch_bounds__(256) void correct2_kernel(
    const float* __restrict__ A_log)
{
    const int bc = blockIdx.x;
    const int b = bc / NC, c = bc - b*NC;
    const int d = threadIdx.x;
    const int l0 = c * CL;

    __shared__ __align__(16) float sC[CL][N_];
    for (int i = d; i < CL*N_; i += 256) {
        int t = i >> 4, j = i & 15;
        sC[t][j] = g_P80[(size_t)(b*L_ + l0 + t)*NP + 48 + j];
    }
    __syncthreads();

    bool fast;
    const float a0 = check_A(A_log, d, fast);
    (void)a0;

    const float* y_ptr  = g_y  + (b*L_ + l0)*D_ + d;
    uint32_t* y16_ptr   = g_y16 + (b*L_ + l0)*D_ + d;
    const float* pc_ptr = g_pc + (b*L_ + l0)*D_ + d;

    if (fast) {
        ull q2[8];
        #pragma unroll
        for (int k = 0; k < 8; ++k) {
            const float qlo = g_hs[((b*NC + c)*N_ + 2*k  )*D_ + d];
            const float qhi = g_hs[((b*NC + c)*N_ + 2*k+1)*D_ + d];
            q2[k] = pack2(qlo, qhi);
        }
        #pragma unroll
        for (int t0 = 0; t0 < CL; t0 += 4) {
            float p1[4], yl[4];
            #pragma unroll
            for (int i = 0; i < 4; ++i) {
                p1[i] = pc_ptr[(t0+i)*D_];
                yl[i] = y_ptr [(t0+i)*D_];
            }
            #pragma unroll
            for (int i = 0; i < 4; ++i) {
                const int t = t0 + i;
                const float psq = p1[i] * p1[i];
                ull pw = pack2(p1[i], psq);
                const ull pstep = pack2(psq, psq);
                const ull* C2 = reinterpret_cast<const ull*>(&sC[t][0]);
                ull corr2 = 0ull;
                #pragma unroll
                for (int k = 0; k < 8; ++k) {
                    corr2 = fma2(mul2(pw, q2[k]), C2[k], corr2);
                    if (k < 7) pw = mul2(pw, pstep);
                }
                float clo, chi; unpack2(corr2, clo, chi);
                y16_ptr[t*D_] = pack_hilo(yl[i] + clo + chi);
            }
        }
    } else {
        float q[N_];
        #pragma unroll
        for (int n = 0; n < N_; ++n)
            q[n] = g_hs[((b*NC + c)*N_ + n)*D_ + d];
        const float* dl_ptr = g_delta + (b*L_ + l0)*D_ + d;
        float a[N_];
        #pragma unroll
        for (int n = 0; n < N_; ++n)
            a[n] = -__expf(__ldg(A_log + d*N_ + n));
        for (int t = 0; t < CL; ++t) {
            const float dl = dl_ptr[t*D_];
            float corr = 0.f;
            #pragma unroll
            for (int n = 0; n < N_; ++n) {
                q[n] *= __expf(dl * a[n]);
                corr = fmaf(q[n], sC[t][n], corr);
            }
            y16_ptr[t*D_] = pack_hilo(y_ptr[t*D_] + corr);
        }
    }
}

// ---------------------------------------------------------------------------
// Kernel 5: out GEMM — pipelined split-bf16 (R15 version, unchanged).
// ---------------------------------------------------------------------------
__global__ __launch_bounds__(256) void gemm_mma_kernel(float* __restrict__ out)
{
    extern __shared__ __nv_bfloat16 sm[];
    __nv_bfloat16* sA_hi = sm;
    __nv_bfloat16* sA_lo = sm + 128*GP;
    __nv_bfloat16* sB_hi = sm + 2*128*GP;
    __nv_bfloat16* sB_lo = sm + 3*128*GP;

    const int tid  = threadIdx.x;
    const int wid  = tid >> 5;
    const int lane = tid & 31;
    const int gid  = lane >> 2;
    const int t4   = lane & 3;

    const int j0 = blockIdx.x * 128;
    const int m0 = blockIdx.y * 128;
    const int wm = (wid >> 2) * 64;
    const int wn = (wid & 3) * 32;

    float acc[4][4][4];
    #pragma unroll
    for (int i = 0; i < 4; ++i)
        #pragma unroll
        for (int j = 0; j < 4; ++j)
            #pragma unroll
            for (int q = 0; q < 4; ++q) acc[i][j][q] = 0.f;

    const int lrow = tid >> 5;
    const int lpc  = tid & 31;

    uint2 pa[16], pb[16];
    #pragma unroll
    for (int rr = 0; rr < 16; ++rr) {
        const int row = lrow + rr*8;
        pa[rr] = *reinterpret_cast<const uint2*>(g_y16 + (m0 + row)*D_ + lpc*2);
        pb[rr] = *reinterpret_cast<const uint2*>(g_W16 + (j0 + row)*D_ + lpc*2);
    }

    for (int kc = 0; kc < 256; kc += 64) {
        #pragma unroll
        for (int rr = 0; rr < 16; ++rr) {
            const int row = lrow + rr*8;
            const int soff = row*GP + lpc*2;
            *reinterpret_cast<uint32_t*>(sA_hi + soff) = __byte_perm(pa[rr].x, pa[rr].y, 0x5410);
            *reinterpret_cast<uint32_t*>(sA_lo + soff) = __byte_perm(pa[rr].x, pa[rr].y, 0x7632);
            *reinterpret_cast<uint32_t*>(sB_hi + soff) = __byte_perm(pb[rr].x, pb[rr].y, 0x5410);
            *reinterpret_cast<uint32_t*>(sB_lo + soff) = __byte_perm(pb[rr].x, pb[rr].y, 0x7632);
        }
        __syncthreads();

        if (kc < 192) {
            #pragma unroll
            for (int rr = 0; rr < 16; ++rr) {
                const int row = lrow + rr*8;
                pa[rr] = *reinterpret_cast<const uint2*>(
                    g_y16 + (m0 + row)*D_ + kc + 64 + lpc*2);
                pb[rr] = *reinterpret_cast<const uint2*>(
                    g_W16 + (j0 + row)*D_ + kc + 64 + lpc*2);
            }
        }

        #pragma unroll
        for (int ks = 0; ks < 4; ++ks) {
            const int k0 = ks*16;
            uint32_t a_hi[4][4], a_lo[4][4], b_hi[4][2], b_lo[4][2];
            #pragma unroll
            for (int mf = 0; mf < 4; ++mf) {
                const int r0 = wm + mf*16 + gid;
                const int c0 = k0 + t4*2;
                a_hi[mf][0] = *reinterpret_cast<const uint32_t*>(sA_hi + (r0    )*GP + c0    );
                a_hi[mf][1] = *reinterpret_cast<const uint32_t*>(sA_hi + (r0 + 8)*GP + c0    );
                a_hi[mf][2] = *reinterpret_cast<const uint32_t*>(sA_hi + (r0    )*GP + c0 + 8);
                a_hi[mf][3] = *reinterpret_cast<const uint32_t*>(sA_hi + (r0 + 8)*GP + c0 + 8);
                a_lo[mf][0] = *reinterpret_cast<const uint32_t*>(sA_lo + (r0    )*GP + c0    );
                a_lo[mf][1] = *reinterpret_cast<const uint32_t*>(sA_lo + (r0 + 8)*GP + c0    );
                a_lo[mf][2] = *reinterpret_cast<const uint32_t*>(sA_lo + (r0    )*GP + c0 + 8);
                a_lo[mf][3] = *reinterpret_cast<const uint32_t*>(sA_lo + (r0 + 8)*GP + c0 + 8);
            }
            #pragma unroll
            for (int nf = 0; nf < 4; ++nf) {
                const int nr = wn + nf*8 + gid;
                const int c0 = k0 + t4*2;
                b_hi[nf][0] = *reinterpret_cast<const uint32_t*>(sB_hi + nr*GP + c0    );
                b_hi[nf][1] = *reinterpret_cast<const uint32_t*>(sB_hi + nr*GP + c0 + 8);
                b_lo[nf][0] = *reinterpret_cast<const uint32_t*>(sB_lo + nr*GP + c0    );
                b_lo[nf][1] = *reinterpret_cast<const uint32_t*>(sB_lo + nr*GP + c0 + 8);
            }
            #pragma unroll
            for (int mf = 0; mf < 4; ++mf)
                #pragma unroll
                for (int nf = 0; nf < 4; ++nf) {
                    mma_bf16(acc[mf][nf], a_hi[mf], b_hi[nf]);
                    mma_bf16(acc[mf][nf], a_hi[mf], b_lo[nf]);
                    mma_bf16(acc[mf][nf], a_lo[mf], b_hi[nf]);
                }
        }
        __syncthreads();
    }

    #pragma unroll
    for (int mf = 0; mf < 4; ++mf) {
        const int mrow = m0 + wm + mf*16 + gid;
        #pragma unroll
        for (int nf = 0; nf < 4; ++nf) {
            const int ncol = j0 + wn + nf*8 + t4*2;
            *reinterpret_cast<float2*>(out + (size_t)mrow*D_ + ncol) =
                make_float2(acc[mf][nf][0], acc[mf][nf][1]);
            *reinterpret_cast<float2*>(out + (size_t)(mrow + 8)*D_ + ncol) =
                make_float2(acc[mf][nf][2], acc[mf][nf][3]);
        }
    }
}

// ---------------------------------------------------------------------------
extern "C" void kernel_launch(void* const* d_in, const int* in_sizes, int n_in,
                              void* d_out, int out_size)
{
    const float* x     = (const float*)d_in[0];
    const float* Wxp   = (const float*)d_in[1];
    const float* Wxb   = (const float*)d_in[2];
    const float* Wdt   = (const float*)d_in[3];
    const float* bdt   = (const float*)d_in[4];
    const float* A_log = (const float*)d_in[5];
    const float* Dskip = (const float*)d_in[6];
    const float* Wout  = (const float*)d_in[7];
    float* out = (float*)d_out;

    const int GEMM_SMEM = 4 * 128 * GP * (int)sizeof(__nv_bfloat16);   // 73728 B
    const int PROJ_SMEM = (2*64 + 2*128) * GP * (int)sizeof(__nv_bfloat16); // 55296 B
    cudaFuncSetAttribute(gemm_mma_kernel,
                         cudaFuncAttributeMaxDynamicSharedMemorySize, GEMM_SMEM);
    cudaFuncSetAttribute(projgemm_kernel,
                         cudaFuncAttributeMaxDynamicSharedMemorySize, PROJ_SMEM);

    projgemm_kernel<<<dim3(1, 256), 256, PROJ_SMEM>>>(x, Wxp, Wxb, Wout);
    scan_kernel    <<<B_*NC, 256>>>(x, Wdt, bdt, A_log, Dskip);
    combine_kernel <<<B_*N_, 1024>>>();
    correct2_kernel<<<B_*NC, 256>>>(A_log);
    gemm_mma_kernel<<<dim3(2, 128), 256, GEMM_SMEM>>>(out);
}